// round 5
// baseline (speedup 1.0000x reference)
#include <cuda_runtime.h>
#include <cstdint>

#define NIMG 32          // 16 ref + 16 tgt
#define B_   16
#define H_   512
#define W_   512
#define HW_  (H_*W_)

// ---------------- scratch (device globals: allocation-free) ----------------
__device__ float         g_lum[NIMG * HW_];   // 33.5 MB
__device__ unsigned char g_ed [NIMG * HW_];   // 8.4 MB  (bit0 = e, bit1 = d)
__device__ float         g_acc[NIMG * 4];     // vp_sum, np, vb_sum, nb

// ---------------- K1: luminance + Sobel + edge + 5x5 dilation (fused) -------
// block (32,8), 32x32 output tile. lum smem halo 3; E smem halo 2 (OOB => 0,
// matching -inf-padded reduce_window); separable OR dilation.
// Also zeroes g_acc (block (0,0,0)) so no separate k_zero launch is needed.
__global__ void k_edges(const float* __restrict__ ref, const float* __restrict__ tgt)
{
    const int img = blockIdx.z;
    const float* src = (img < B_) ? (ref + (size_t)img * 3 * HW_)
                                  : (tgt + (size_t)(img - B_) * 3 * HW_);
    __shared__ float         sl[38][40];
    __shared__ unsigned char se[36][40];
    __shared__ unsigned char sv[32][40];

    const int tx0 = blockIdx.x * 32, ty0 = blockIdx.y * 32;
    const int tid = threadIdx.y * 32 + threadIdx.x;

    if (blockIdx.x == 0 && blockIdx.y == 0 && img == 0 && tid < NIMG * 4)
        g_acc[tid] = 0.f;

    // lum with halo 3 (zero-padded, matches SAME conv)
    for (int idx = tid; idx < 38 * 38; idx += 256) {
        int sy = idx / 38, sx = idx % 38;
        int gy = ty0 - 3 + sy, gx = tx0 - 3 + sx;
        float v = 0.f;
        if (gy >= 0 && gy < H_ && gx >= 0 && gx < W_) {
            int p = gy * W_ + gx;
            v = 0.299f * src[p] + 0.587f * src[HW_ + p] + 0.114f * src[2 * HW_ + p];
        }
        sl[sy][sx] = v;
    }
    __syncthreads();

    // E with halo 2; OOB pixels forced to 0 (dilation only sees in-image E)
    for (int idx = tid; idx < 36 * 36; idx += 256) {
        int ey = idx / 36, ex = idx % 36;
        int gy = ty0 - 2 + ey, gx = tx0 - 2 + ex;
        unsigned char ev = 0;
        if (gy >= 0 && gy < H_ && gx >= 0 && gx < W_) {
            float a00 = sl[ey  ][ex], a01 = sl[ey  ][ex+1], a02 = sl[ey  ][ex+2];
            float a10 = sl[ey+1][ex],                        a12 = sl[ey+1][ex+2];
            float a20 = sl[ey+2][ex], a21 = sl[ey+2][ex+1], a22 = sl[ey+2][ex+2];
            float gxv = (a02 - a00) + 2.f * (a12 - a10) + (a22 - a20);
            float gyv = (a20 - a00) + 2.f * (a21 - a01) + (a22 - a02);
            float g2  = gxv * gxv + gyv * gyv + 1e-12f;  // sqrt(g2)>0.1 <=> g2>0.01
            ev = (g2 > 0.01f) ? (unsigned char)1 : (unsigned char)0;
        }
        se[ey][ex] = ev;
    }
    __syncthreads();

    // vertical OR (5 rows)
    for (int idx = tid; idx < 32 * 36; idx += 256) {
        int y = idx / 36, ex = idx % 36;
        sv[y][ex] = (unsigned char)(se[y][ex] | se[y+1][ex] | se[y+2][ex] |
                                    se[y+3][ex] | se[y+4][ex]);
    }
    __syncthreads();

    float*         lum_out = g_lum + (size_t)img * HW_;
    unsigned char* ed_out  = g_ed  + (size_t)img * HW_;

#pragma unroll
    for (int k = 0; k < 4; k++) {
        int yl = threadIdx.y + 8 * k, xl = threadIdx.x;
        unsigned char d = (unsigned char)(sv[yl][xl] | sv[yl][xl+1] | sv[yl][xl+2] |
                                          sv[yl][xl+3] | sv[yl][xl+4]);
        int p = (ty0 + yl) * W_ + (tx0 + xl);
        lum_out[p] = sl[yl + 3][xl + 3];
        ed_out[p]  = (unsigned char)(se[yl + 2][xl + 2] | (d << 1));
    }
}

// ---------------- K2: fused 7x7 box variance + per-image reduction ----------
// Warp-autonomous, 4 cols/thread, full 512-px width per 128-thread block.
// Software-prefetches the next row; departing row (r-7) is an L1 hit.
// Horizontal pass split into two 3-quantity groups (prox, bg) to cut live
// registers and reach 5 blocks/SM.
#define ROWS_IN 38   // 32 output rows + 6 halo rows
__global__ __launch_bounds__(128, 5) void k_variance()
{
    const int img = blockIdx.y;
    const int y0  = blockIdx.x * 32;
    const int t   = threadIdx.x;
    const int w   = t >> 5, l = t & 31;
    const int c0  = t * 4;

    const float*         lum = g_lum + (size_t)img * HW_;
    const unsigned char* ed  = g_ed  + (size_t)img * HW_;

    // packed e/d ring; OOB rows = 0x03 per byte (e=d=1 -> both masks 0)
    unsigned edr[7];
#pragma unroll
    for (int s = 0; s < 7; s++) edr[s] = 0x03030303u;

    float vs[6][4];
#pragma unroll
    for (int q = 0; q < 6; q++)
#pragma unroll
        for (int c = 0; c < 4; c++) vs[q][c] = 0.f;

    float accVp = 0.f, accNp = 0.f, accVb = 0.f, accNb = 0.f;

    __shared__ float sufB[2][4][6][3];
    __shared__ float preB[2][4][6][3];

    // ---- preload row i=0 ----
    float4   xv = make_float4(0.f, 0.f, 0.f, 0.f);
    unsigned edu = 0x03030303u;
    {
        const int r0 = y0 - 3;
        if (r0 >= 0 && r0 < H_) {
            xv  = *(const float4*)(lum + r0 * W_ + c0);
            edu = *(const unsigned*)(ed + r0 * W_ + c0);
        }
    }

#pragma unroll 1
    for (int outer = 0; outer < 6; outer++) {
#pragma unroll
        for (int j = 0; j < 7; j++) {
            const int i = outer * 7 + j;
            if (i >= ROWS_IN) break;              // uniform
            const int r = y0 - 3 + i;

            // ---- prefetch row i+1 ----
            float4   xvn = make_float4(0.f, 0.f, 0.f, 0.f);
            unsigned edn = 0x03030303u;
            const int rn = r + 1;
            if (i + 1 < ROWS_IN && rn >= 0 && rn < H_) {
                xvn = *(const float4*)(lum + rn * W_ + c0);
                edn = *(const unsigned*)(ed + rn * W_ + c0);
            }

            // ---- departing row (r-7): L1 hit ----
            const int ro = r - 7;
            float4 xo4 = make_float4(0.f, 0.f, 0.f, 0.f);
            if (ro >= 0 && ro < H_)
                xo4 = *(const float4*)(lum + ro * W_ + c0);

            // ---- vertical running-sum update ----
#pragma unroll
            for (int c = 0; c < 4; c++) {
                unsigned bn = (edu    >> (8 * c)) & 3u;
                unsigned bo = (edr[j] >> (8 * c)) & 3u;
                float xn  = (&xv.x)[c];
                float xo  = (&xo4.x)[c];
                float mpn = (bn == 2u) ? 1.f : 0.f;
                float mbn = (bn == 0u) ? 1.f : 0.f;
                float mpo = (bo == 2u) ? 1.f : 0.f;
                float mbo = (bo == 0u) ? 1.f : 0.f;
                vs[0][c] += mpn - mpo;
                vs[1][c] += xn * mpn - xo * mpo;
                vs[2][c] += xn * xn * mpn - xo * xo * mpo;
                vs[3][c] += mbn - mbo;
                vs[4][c] += xn * mbn - xo * mbo;
                vs[5][c] += xn * xn * mbn - xo * xo * mbo;
            }
            edr[j] = edu;

            if (i >= 6) {
                const int par = i & 1;
                // ---- publish warp-boundary halos (prefix sums inline from vs) ----
                if (l == 31) {
#pragma unroll
                    for (int q = 0; q < 6; q++) {
                        sufB[par][w][q][0] = vs[q][1] + vs[q][2] + vs[q][3];
                        sufB[par][w][q][1] = vs[q][2] + vs[q][3];
                        sufB[par][w][q][2] = vs[q][3];
                    }
                }
                if (l == 0) {
#pragma unroll
                    for (int q = 0; q < 6; q++) {
                        preB[par][w][q][0] = vs[q][0];
                        preB[par][w][q][1] = vs[q][0] + vs[q][1];
                        preB[par][w][q][2] = vs[q][0] + vs[q][1] + vs[q][2];
                    }
                }
                __syncthreads();

                const int jc = (j + 4) % 7;   // center row slot
                unsigned edc = edr[jc];

                // ---- two 3-quantity groups: 0 = prox, 1 = bg ----
#pragma unroll
                for (int g = 0; g < 2; g++) {
                    float Wn[3][4];
#pragma unroll
                    for (int qq = 0; qq < 3; qq++) {
                        const int q = 3 * g + qq;
                        float p0 = vs[q][0];
                        float p1 = p0 + vs[q][1];
                        float p2 = p1 + vs[q][2];
                        float T  = p2 + vs[q][3];
                        float s1 = T - p0, s2 = T - p1, s3 = T - p2;
                        float ls1 = __shfl_up_sync(0xffffffffu, s1, 1);
                        float ls2 = __shfl_up_sync(0xffffffffu, s2, 1);
                        float ls3 = __shfl_up_sync(0xffffffffu, s3, 1);
                        float rp0 = __shfl_down_sync(0xffffffffu, p0, 1);
                        float rp1 = __shfl_down_sync(0xffffffffu, p1, 1);
                        float rp2 = __shfl_down_sync(0xffffffffu, p2, 1);
                        if (l == 0) {
                            ls1 = (w > 0) ? sufB[par][w - 1][q][0] : 0.f;
                            ls2 = (w > 0) ? sufB[par][w - 1][q][1] : 0.f;
                            ls3 = (w > 0) ? sufB[par][w - 1][q][2] : 0.f;
                        }
                        if (l == 31) {
                            rp0 = (w < 3) ? preB[par][w + 1][q][0] : 0.f;
                            rp1 = (w < 3) ? preB[par][w + 1][q][1] : 0.f;
                            rp2 = (w < 3) ? preB[par][w + 1][q][2] : 0.f;
                        }
                        Wn[qq][0] = ls1 + T;
                        Wn[qq][1] = ls2 + T + rp0;
                        Wn[qq][2] = ls3 + T + rp1;
                        Wn[qq][3] = T + rp2;
                    }
                    float aV = 0.f, aN = 0.f;
#pragma unroll
                    for (int c = 0; c < 4; c++) {
                        float cnt = fmaxf(Wn[0][c], 1.f);
                        float rcn = __fdividef(1.f, cnt);
                        float mu  = Wn[1][c] * rcn;
                        float var = fmaxf(Wn[2][c] * rcn - mu * mu, 0.f);
                        unsigned bc = (edc >> (8 * c)) & 3u;
                        float m = (g == 0) ? ((bc == 2u) ? 1.f : 0.f)
                                           : ((bc == 0u) ? 1.f : 0.f);
                        aV += m * var; aN += m;
                    }
                    if (g == 0) { accVp += aV; accNp += aN; }
                    else        { accVb += aV; accNb += aN; }
                }
            }

            xv = xvn; edu = edn;
        }
    }

#pragma unroll
    for (int off = 16; off > 0; off >>= 1) {
        accVp += __shfl_down_sync(0xffffffffu, accVp, off);
        accNp += __shfl_down_sync(0xffffffffu, accNp, off);
        accVb += __shfl_down_sync(0xffffffffu, accVb, off);
        accNb += __shfl_down_sync(0xffffffffu, accNb, off);
    }
    if (l == 0) {
        atomicAdd(&g_acc[img * 4 + 0], accVp);
        atomicAdd(&g_acc[img * 4 + 1], accNp);
        atomicAdd(&g_acc[img * 4 + 2], accVb);
        atomicAdd(&g_acc[img * 4 + 3], accNb);
    }
}

// ---------------- K3: flags + output = clip(ringing_tgt - ringing_ref, 0) ---
__global__ void k_output(float* __restrict__ out)
{
    int idx = blockIdx.x * blockDim.x + threadIdx.x;
    const int n4 = B_ * HW_ / 4;
    if (idx >= n4) return;
    int b  = idx / (HW_ / 4);
    int p4 = idx % (HW_ / 4);

    // per-image ringing flags recomputed inline (uniform L1-broadcast loads)
    float vpr = g_acc[b * 4 + 0],        npr = g_acc[b * 4 + 1];
    float vbr = g_acc[b * 4 + 2],        nbr = g_acc[b * 4 + 3];
    float vpt = g_acc[(b + B_) * 4 + 0], npt = g_acc[(b + B_) * 4 + 1];
    float vbt = g_acc[(b + B_) * 4 + 2], nbt = g_acc[(b + B_) * 4 + 3];
    float fr = ((vpr / fmaxf(npr, 1.f)) / (vbr / fmaxf(nbr, 1.f) + 1e-12f) > 2.0f) ? 1.f : 0.f;
    float ft = ((vpt / fmaxf(npt, 1.f)) / (vbt / fmaxf(nbt, 1.f) + 1e-12f) > 2.0f) ? 1.f : 0.f;

    const uchar4* edr4 = (const uchar4*)(g_ed + (size_t)b * HW_);
    const uchar4* edt4 = (const uchar4*)(g_ed + (size_t)(b + B_) * HW_);
    uchar4 r4 = edr4[p4], t4 = edt4[p4];

    // byte==2 (d=1,e=0) <=> pixel in M_prox
    float4 o;
    o.x = fmaxf((t4.x == 2 ? ft : 0.f) - (r4.x == 2 ? fr : 0.f), 0.f);
    o.y = fmaxf((t4.y == 2 ? ft : 0.f) - (r4.y == 2 ? fr : 0.f), 0.f);
    o.z = fmaxf((t4.z == 2 ? ft : 0.f) - (r4.z == 2 ? fr : 0.f), 0.f);
    o.w = fmaxf((t4.w == 2 ? ft : 0.f) - (r4.w == 2 ? fr : 0.f), 0.f);
    ((float4*)out)[idx] = o;
}

// ---------------- launch ----------------
extern "C" void kernel_launch(void* const* d_in, const int* in_sizes, int n_in,
                              void* d_out, int out_size)
{
    const float* ref = (const float*)d_in[0];
    const float* tgt = (const float*)d_in[1];

    dim3 b1(32, 8);
    dim3 g1(W_ / 32, H_ / 32, NIMG);
    k_edges<<<g1, b1>>>(ref, tgt);

    k_variance<<<dim3(16, NIMG), 128>>>();

    const int n4 = B_ * HW_ / 4;
    k_output<<<(n4 + 255) / 256, 256>>>((float*)d_out);
}

// round 7
// speedup vs baseline: 1.1083x; 1.1083x over previous
#include <cuda_runtime.h>
#include <cstdint>

#define NIMG 32          // 16 ref + 16 tgt
#define B_   16
#define H_   512
#define W_   512
#define HW_  (H_*W_)

// ---------------- scratch (device globals: allocation-free) ----------------
__device__ float         g_lum[NIMG * HW_];   // 33.5 MB
__device__ unsigned char g_ed [NIMG * HW_];   // 8.4 MB  (bit0 = e, bit1 = d)
__device__ float         g_acc[NIMG * 4];     // vp_sum, np, vb_sum, nb

// ---------------- K1: luminance + Sobel + edge + 5x5 dilation (fused) -------
// block (32,8)=256 thr, 32x32 output tile. All phases vectorized:
//   lum halo:  38 rows x 10 float4-chunks (x-chunks 4-aligned => all-in or all-out)
//   E:         4-px strips, 6 float4 LDS per strip, packed u32 store
//   vert OR:   u32 chunks (5 LDS + 1 STS per 4 px)
//   horiz OR:  byte-parallel register OR of an 8-byte window
// Also zeroes g_acc (block (0,0,0)).
__global__ void k_edges(const float* __restrict__ ref, const float* __restrict__ tgt)
{
    const int img = blockIdx.z;
    const float* src = (img < B_) ? (ref + (size_t)img * 3 * HW_)
                                  : (tgt + (size_t)(img - B_) * 3 * HW_);
    __shared__ float         sl[38][40];   // lum, cols gx = tx0-4 .. tx0+35
    __shared__ unsigned char se[36][40];   // E,   cols gx = tx0-2 .. tx0+33 (idx 0..35)
    __shared__ unsigned char sv[32][40];   // vert-OR of E

    const int tx0 = blockIdx.x * 32, ty0 = blockIdx.y * 32;
    const int tid = threadIdx.y * 32 + threadIdx.x;

    if (blockIdx.x == 0 && blockIdx.y == 0 && img == 0 && tid < NIMG * 4)
        g_acc[tid] = 0.f;

    // ---- phase 1: luminance halo load, float4 per channel ----
    // 38 rows x 10 chunks = 380 units
    for (int idx = tid; idx < 380; idx += 256) {
        int sy = idx / 10, cx = idx % 10;
        int gy = ty0 - 3 + sy;
        int gx0 = tx0 - 4 + cx * 4;
        float4 v = make_float4(0.f, 0.f, 0.f, 0.f);
        if (gy >= 0 && gy < H_ && gx0 >= 0 && gx0 < W_) {
            int p = gy * W_ + gx0;
            float4 r4 = *(const float4*)(src + p);
            float4 g4 = *(const float4*)(src + HW_ + p);
            float4 b4 = *(const float4*)(src + 2 * HW_ + p);
            v.x = 0.299f * r4.x + 0.587f * g4.x + 0.114f * b4.x;
            v.y = 0.299f * r4.y + 0.587f * g4.y + 0.114f * b4.y;
            v.z = 0.299f * r4.z + 0.587f * g4.z + 0.114f * b4.z;
            v.w = 0.299f * r4.w + 0.587f * g4.w + 0.114f * b4.w;
        }
        *(float4*)&sl[sy][cx * 4] = v;
    }
    __syncthreads();

    // ---- phase 2: Sobel + threshold, 4-px strips ----
    // 36 rows x 9 strips = 324 units; strip sxc covers exi = 4sxc..4sxc+3
    // lum window: rows ey..ey+2, cols 4sxc..4sxc+7 (two float4 per row)
    for (int idx = tid; idx < 324; idx += 256) {
        int ey = idx / 9, sxc = idx % 9;
        int gy = ty0 - 2 + ey;
        float L[3][8];
#pragma unroll
        for (int rr = 0; rr < 3; rr++) {
            *(float4*)&L[rr][0] = *(const float4*)&sl[ey + rr][4 * sxc];
            *(float4*)&L[rr][4] = *(const float4*)&sl[ey + rr][4 * sxc + 4];
        }
        unsigned epack = 0;
        if (gy >= 0 && gy < H_) {
#pragma unroll
            for (int c = 0; c < 4; c++) {
                int gx = tx0 - 2 + 4 * sxc + c;
                if (gx >= 0 && gx < W_) {
                    float gxv = (L[0][c+3] - L[0][c+1])
                              + 2.f * (L[1][c+3] - L[1][c+1])
                              + (L[2][c+3] - L[2][c+1]);
                    float gyv = (L[2][c+1] - L[0][c+1])
                              + 2.f * (L[2][c+2] - L[0][c+2])
                              + (L[2][c+3] - L[0][c+3]);
                    float g2 = gxv * gxv + gyv * gyv + 1e-12f; // sqrt>0.1 <=> >0.01
                    if (g2 > 0.01f) epack |= 1u << (8 * c);
                }
            }
        }
        *(unsigned*)&se[ey][4 * sxc] = epack;
    }
    __syncthreads();

    // ---- phase 3: vertical OR over 5 rows, u32 chunks ----
    // 32 rows x 9 chunks = 288 units
    for (int idx = tid; idx < 288; idx += 256) {
        int y = idx / 9, sxc = idx % 9;
        unsigned o = *(const unsigned*)&se[y    ][4 * sxc]
                   | *(const unsigned*)&se[y + 1][4 * sxc]
                   | *(const unsigned*)&se[y + 2][4 * sxc]
                   | *(const unsigned*)&se[y + 3][4 * sxc]
                   | *(const unsigned*)&se[y + 4][4 * sxc];
        *(unsigned*)&sv[y][4 * sxc] = o;
    }
    __syncthreads();

    // ---- phase 4: horizontal OR + pack ed + write lum/ed ----
    // 256 threads = 32 rows x 8 chunks, 4 px each
    {
        int yl  = tid >> 3;
        int xl  = (tid & 7) * 4;
        unsigned u0 = *(const unsigned*)&sv[yl][xl];
        unsigned u1 = *(const unsigned*)&sv[yl][xl + 4];
        unsigned v1 = (u0 >> 8)  | (u1 << 24);
        unsigned v2 = (u0 >> 16) | (u1 << 16);
        unsigned v3 = (u0 >> 24) | (u1 << 8);
        unsigned d  = u0 | v1 | v2 | v3 | u1;      // byte c = OR bytes c..c+4

        unsigned s0 = *(const unsigned*)&se[yl + 2][xl];
        unsigned s1 = *(const unsigned*)&se[yl + 2][xl + 4];
        unsigned e  = (s0 >> 16) | (s1 << 16);      // center E bytes

        unsigned ed = e | (d << 1);

        int p = (ty0 + yl) * W_ + (tx0 + xl);
        *(unsigned*)(g_ed + (size_t)img * HW_ + p) = ed;
        *(float4*)(g_lum + (size_t)img * HW_ + p) = *(const float4*)&sl[yl + 3][xl + 4];
    }
}

// ---------------- K2: fused 7x7 box variance + per-image reduction ----------
// Warp-autonomous, 4 cols/thread, full 512-px width per 128-thread block.
// Software-prefetches the next row; departing row (r-7) is an L1 hit.
#define ROWS_IN 38   // 32 output rows + 6 halo rows
__global__ __launch_bounds__(128, 5) void k_variance()
{
    const int img = blockIdx.y;
    const int y0  = blockIdx.x * 32;
    const int t   = threadIdx.x;
    const int w   = t >> 5, l = t & 31;
    const int c0  = t * 4;

    const float*         lum = g_lum + (size_t)img * HW_;
    const unsigned char* ed  = g_ed  + (size_t)img * HW_;

    // packed e/d ring; OOB rows = 0x03 per byte (e=d=1 -> both masks 0)
    unsigned edr[7];
#pragma unroll
    for (int s = 0; s < 7; s++) edr[s] = 0x03030303u;

    float vs[6][4];
#pragma unroll
    for (int q = 0; q < 6; q++)
#pragma unroll
        for (int c = 0; c < 4; c++) vs[q][c] = 0.f;

    float accVp = 0.f, accNp = 0.f, accVb = 0.f, accNb = 0.f;

    __shared__ float sufB[2][4][6][3];
    __shared__ float preB[2][4][6][3];

    // ---- preload row i=0 ----
    float4   xv = make_float4(0.f, 0.f, 0.f, 0.f);
    unsigned edu = 0x03030303u;
    {
        const int r0 = y0 - 3;
        if (r0 >= 0 && r0 < H_) {
            xv  = *(const float4*)(lum + r0 * W_ + c0);
            edu = *(const unsigned*)(ed + r0 * W_ + c0);
        }
    }

#pragma unroll 1
    for (int outer = 0; outer < 6; outer++) {
#pragma unroll
        for (int j = 0; j < 7; j++) {
            const int i = outer * 7 + j;
            if (i >= ROWS_IN) break;              // uniform
            const int r = y0 - 3 + i;

            // ---- prefetch row i+1 ----
            float4   xvn = make_float4(0.f, 0.f, 0.f, 0.f);
            unsigned edn = 0x03030303u;
            const int rn = r + 1;
            if (i + 1 < ROWS_IN && rn >= 0 && rn < H_) {
                xvn = *(const float4*)(lum + rn * W_ + c0);
                edn = *(const unsigned*)(ed + rn * W_ + c0);
            }

            // ---- departing row (r-7): L1 hit ----
            const int ro = r - 7;
            float4 xo4 = make_float4(0.f, 0.f, 0.f, 0.f);
            if (ro >= 0 && ro < H_)
                xo4 = *(const float4*)(lum + ro * W_ + c0);

            // ---- vertical running-sum update ----
#pragma unroll
            for (int c = 0; c < 4; c++) {
                unsigned bn = (edu    >> (8 * c)) & 3u;
                unsigned bo = (edr[j] >> (8 * c)) & 3u;
                float xn  = (&xv.x)[c];
                float xo  = (&xo4.x)[c];
                float mpn = (bn == 2u) ? 1.f : 0.f;
                float mbn = (bn == 0u) ? 1.f : 0.f;
                float mpo = (bo == 2u) ? 1.f : 0.f;
                float mbo = (bo == 0u) ? 1.f : 0.f;
                vs[0][c] += mpn - mpo;
                vs[1][c] += xn * mpn - xo * mpo;
                vs[2][c] += xn * xn * mpn - xo * xo * mpo;
                vs[3][c] += mbn - mbo;
                vs[4][c] += xn * mbn - xo * mbo;
                vs[5][c] += xn * xn * mbn - xo * xo * mbo;
            }
            edr[j] = edu;

            if (i >= 6) {
                const int par = i & 1;
                if (l == 31) {
#pragma unroll
                    for (int q = 0; q < 6; q++) {
                        sufB[par][w][q][0] = vs[q][1] + vs[q][2] + vs[q][3];
                        sufB[par][w][q][1] = vs[q][2] + vs[q][3];
                        sufB[par][w][q][2] = vs[q][3];
                    }
                }
                if (l == 0) {
#pragma unroll
                    for (int q = 0; q < 6; q++) {
                        preB[par][w][q][0] = vs[q][0];
                        preB[par][w][q][1] = vs[q][0] + vs[q][1];
                        preB[par][w][q][2] = vs[q][0] + vs[q][1] + vs[q][2];
                    }
                }
                __syncthreads();

                const int jc = (j + 4) % 7;   // center row slot
                unsigned edc = edr[jc];

#pragma unroll
                for (int g = 0; g < 2; g++) {
                    float Wn[3][4];
#pragma unroll
                    for (int qq = 0; qq < 3; qq++) {
                        const int q = 3 * g + qq;
                        float p0 = vs[q][0];
                        float p1 = p0 + vs[q][1];
                        float p2 = p1 + vs[q][2];
                        float T  = p2 + vs[q][3];
                        float s1 = T - p0, s2 = T - p1, s3 = T - p2;
                        float ls1 = __shfl_up_sync(0xffffffffu, s1, 1);
                        float ls2 = __shfl_up_sync(0xffffffffu, s2, 1);
                        float ls3 = __shfl_up_sync(0xffffffffu, s3, 1);
                        float rp0 = __shfl_down_sync(0xffffffffu, p0, 1);
                        float rp1 = __shfl_down_sync(0xffffffffu, p1, 1);
                        float rp2 = __shfl_down_sync(0xffffffffu, p2, 1);
                        if (l == 0) {
                            ls1 = (w > 0) ? sufB[par][w - 1][q][0] : 0.f;
                            ls2 = (w > 0) ? sufB[par][w - 1][q][1] : 0.f;
                            ls3 = (w > 0) ? sufB[par][w - 1][q][2] : 0.f;
                        }
                        if (l == 31) {
                            rp0 = (w < 3) ? preB[par][w + 1][q][0] : 0.f;
                            rp1 = (w < 3) ? preB[par][w + 1][q][1] : 0.f;
                            rp2 = (w < 3) ? preB[par][w + 1][q][2] : 0.f;
                        }
                        Wn[qq][0] = ls1 + T;
                        Wn[qq][1] = ls2 + T + rp0;
                        Wn[qq][2] = ls3 + T + rp1;
                        Wn[qq][3] = T + rp2;
                    }
                    float aV = 0.f, aN = 0.f;
#pragma unroll
                    for (int c = 0; c < 4; c++) {
                        float cnt = fmaxf(Wn[0][c], 1.f);
                        float rcn = __fdividef(1.f, cnt);
                        float mu  = Wn[1][c] * rcn;
                        float var = fmaxf(Wn[2][c] * rcn - mu * mu, 0.f);
                        unsigned bc = (edc >> (8 * c)) & 3u;
                        float m = (g == 0) ? ((bc == 2u) ? 1.f : 0.f)
                                           : ((bc == 0u) ? 1.f : 0.f);
                        aV += m * var; aN += m;
                    }
                    if (g == 0) { accVp += aV; accNp += aN; }
                    else        { accVb += aV; accNb += aN; }
                }
            }

            xv = xvn; edu = edn;
        }
    }

#pragma unroll
    for (int off = 16; off > 0; off >>= 1) {
        accVp += __shfl_down_sync(0xffffffffu, accVp, off);
        accNp += __shfl_down_sync(0xffffffffu, accNp, off);
        accVb += __shfl_down_sync(0xffffffffu, accVb, off);
        accNb += __shfl_down_sync(0xffffffffu, accNb, off);
    }
    if (l == 0) {
        atomicAdd(&g_acc[img * 4 + 0], accVp);
        atomicAdd(&g_acc[img * 4 + 1], accNp);
        atomicAdd(&g_acc[img * 4 + 2], accVb);
        atomicAdd(&g_acc[img * 4 + 3], accNb);
    }
}

// ---------------- K3: flags + output = clip(ringing_tgt - ringing_ref, 0) ---
__global__ void k_output(float* __restrict__ out)
{
    int idx = blockIdx.x * blockDim.x + threadIdx.x;
    const int n4 = B_ * HW_ / 4;
    if (idx >= n4) return;
    int b  = idx / (HW_ / 4);
    int p4 = idx % (HW_ / 4);

    float vpr = g_acc[b * 4 + 0],        npr = g_acc[b * 4 + 1];
    float vbr = g_acc[b * 4 + 2],        nbr = g_acc[b * 4 + 3];
    float vpt = g_acc[(b + B_) * 4 + 0], npt = g_acc[(b + B_) * 4 + 1];
    float vbt = g_acc[(b + B_) * 4 + 2], nbt = g_acc[(b + B_) * 4 + 3];
    float fr = ((vpr / fmaxf(npr, 1.f)) / (vbr / fmaxf(nbr, 1.f) + 1e-12f) > 2.0f) ? 1.f : 0.f;
    float ft = ((vpt / fmaxf(npt, 1.f)) / (vbt / fmaxf(nbt, 1.f) + 1e-12f) > 2.0f) ? 1.f : 0.f;

    const uchar4* edr4 = (const uchar4*)(g_ed + (size_t)b * HW_);
    const uchar4* edt4 = (const uchar4*)(g_ed + (size_t)(b + B_) * HW_);
    uchar4 r4 = edr4[p4], t4 = edt4[p4];

    // byte==2 (d=1,e=0) <=> pixel in M_prox
    float4 o;
    o.x = fmaxf((t4.x == 2 ? ft : 0.f) - (r4.x == 2 ? fr : 0.f), 0.f);
    o.y = fmaxf((t4.y == 2 ? ft : 0.f) - (r4.y == 2 ? fr : 0.f), 0.f);
    o.z = fmaxf((t4.z == 2 ? ft : 0.f) - (r4.z == 2 ? fr : 0.f), 0.f);
    o.w = fmaxf((t4.w == 2 ? ft : 0.f) - (r4.w == 2 ? fr : 0.f), 0.f);
    ((float4*)out)[idx] = o;
}

// ---------------- launch ----------------
extern "C" void kernel_launch(void* const* d_in, const int* in_sizes, int n_in,
                              void* d_out, int out_size)
{
    const float* ref = (const float*)d_in[0];
    const float* tgt = (const float*)d_in[1];

    dim3 b1(32, 8);
    dim3 g1(W_ / 32, H_ / 32, NIMG);
    k_edges<<<g1, b1>>>(ref, tgt);

    k_variance<<<dim3(16, NIMG), 128>>>();

    const int n4 = B_ * HW_ / 4;
    k_output<<<(n4 + 255) / 256, 256>>>((float*)d_out);
}

// round 8
// speedup vs baseline: 1.3854x; 1.2500x over previous
#include <cuda_runtime.h>
#include <cstdint>

#define NIMG 32          // 16 ref + 16 tgt
#define B_   16
#define H_   512
#define W_   512
#define HW_  (H_*W_)

// ---------------- scratch (device globals: allocation-free) ----------------
__device__ unsigned char g_ed [NIMG * HW_];   // 8.4 MB  (bit0 = e, bit1 = d)
__device__ float         g_acc[NIMG * 4];     // zero-init at load; re-zeroed by epilogue

// ---------------- K1: fully fused row-streaming kernel ----------------------
// Block: 128 threads, 4 cols/thread = full 512-px width; strip of 32 output rows.
// Per step i (44 steps): load rgb row rl=y0-6+i -> lum (smem ring, depth 12);
// Sobel E row rE=rl-1 (register shift ring, packed u32); vertical OR in regs;
// horizontal OR via parity smem row -> ed row rv=rl-3; 7x7 windowed-variance
// vertical update (edr shift ring) + shfl horizontal + masked accumulate.
#define LRING  12
#define LPITCH 528     // cols -4..515 live at idx 0..519 (pads zero), stride 528

__global__ __launch_bounds__(128) void k_fused(const float* __restrict__ ref,
                                               const float* __restrict__ tgt)
{
    const int img = blockIdx.y;
    const int y0  = blockIdx.x * 32;
    const int t   = threadIdx.x;
    const int w   = t >> 5, l = t & 31;
    const int c0  = t * 4;

    const float* src = (img < B_) ? (ref + (size_t)img * 3 * HW_)
                                  : (tgt + (size_t)(img - B_) * 3 * HW_);
    unsigned char* edout = g_ed + (size_t)img * HW_;

    __shared__ float    slum[LRING][LPITCH];
    __shared__ unsigned vbuf[2][132];          // idx 1+t; [0] and [129] stay 0
    __shared__ float    sufB[2][4][6][3];
    __shared__ float    preB[2][4][6][3];

    // zero smem (pads + never-written halo slots must be 0, not garbage/NaN)
    for (int k = t; k < LRING * LPITCH; k += 128) ((float*)slum)[k] = 0.f;
    for (int k = t; k < 2 * 132; k += 128) ((unsigned*)vbuf)[k] = 0u;
    __syncthreads();

    // E shift ring (newest = e4_4, row rE; e4_0 = rE-4)
    unsigned e4_0 = 0, e4_1 = 0, e4_2 = 0, e4_3 = 0, e4_4 = 0;
    // ed shift ring for variance window (newest = edr6 = row rv)
    unsigned edr0 = 0x03030303u, edr1 = 0x03030303u, edr2 = 0x03030303u,
             edr3 = 0x03030303u, edr4 = 0x03030303u, edr5 = 0x03030303u,
             edr6 = 0x03030303u;

    float vs[6][4];
#pragma unroll
    for (int q = 0; q < 6; q++)
#pragma unroll
        for (int c = 0; c < 4; c++) vs[q][c] = 0.f;

    float accVp = 0.f, accNp = 0.f, accVb = 0.f, accNb = 0.f;

    // prefetch rgb row for step 0
    float4 pr, pg, pb;
    bool pvalid;
    {
        int rl0 = y0 - 6;
        pvalid = (rl0 >= 0 && rl0 < H_);
        if (pvalid) {
            pr = *(const float4*)(src + rl0 * W_ + c0);
            pg = *(const float4*)(src + HW_ + rl0 * W_ + c0);
            pb = *(const float4*)(src + 2 * HW_ + rl0 * W_ + c0);
        }
    }

    int cur = 0;   // lum ring write slot for step i

#pragma unroll 1
    for (int i = 0; i < 44; i++) {
        // ---- lum from prefetched rgb, store to ring ----
        float4 lumv = make_float4(0.f, 0.f, 0.f, 0.f);
        if (pvalid) {
            lumv.x = 0.299f * pr.x + 0.587f * pg.x + 0.114f * pb.x;
            lumv.y = 0.299f * pr.y + 0.587f * pg.y + 0.114f * pb.y;
            lumv.z = 0.299f * pr.z + 0.587f * pg.z + 0.114f * pb.z;
            lumv.w = 0.299f * pr.w + 0.587f * pg.w + 0.114f * pb.w;
        }
        *(float4*)&slum[cur][4 + c0] = lumv;

        // ---- prefetch next rgb row ----
        {
            int rln = y0 - 5 + i;
            pvalid = (i < 43) && (rln >= 0) && (rln < H_);
            if (pvalid) {
                pr = *(const float4*)(src + rln * W_ + c0);
                pg = *(const float4*)(src + HW_ + rln * W_ + c0);
                pb = *(const float4*)(src + 2 * HW_ + rln * W_ + c0);
            }
        }
        __syncthreads();   // A: lum[rl] visible

        // ---- Sobel E row rE = rl-1 = y0-7+i ----
        unsigned epack = 0;
        {
            const int rE = y0 - 7 + i;
            if (i >= 2 && rE >= 0 && rE < H_) {
                int sa = cur - 2; if (sa < 0) sa += LRING;
                int sb = cur - 1; if (sb < 0) sb += LRING;
                float A[6], Bv[6], D[6];
                *(float4*)&A[1]  = *(const float4*)&slum[sa][4 + c0];
                A[0]  = slum[sa][3 + c0];  A[5]  = slum[sa][8 + c0];
                *(float4*)&Bv[1] = *(const float4*)&slum[sb][4 + c0];
                Bv[0] = slum[sb][3 + c0];  Bv[5] = slum[sb][8 + c0];
                *(float4*)&D[1]  = *(const float4*)&slum[cur][4 + c0];
                D[0]  = slum[cur][3 + c0]; D[5]  = slum[cur][8 + c0];
#pragma unroll
                for (int c = 0; c < 4; c++) {
                    float gx = (A[c+2] - A[c]) + 2.f * (Bv[c+2] - Bv[c]) + (D[c+2] - D[c]);
                    float gy = (D[c]   - A[c]) + 2.f * (D[c+1] - A[c+1]) + (D[c+2] - A[c+2]);
                    float g2 = gx * gx + gy * gy + 1e-12f;   // sqrt>0.1 <=> >0.01
                    if (g2 > 0.01f) epack |= 1u << (8 * c);
                }
            }
        }
        e4_0 = e4_1; e4_1 = e4_2; e4_2 = e4_3; e4_3 = e4_4; e4_4 = epack;

        if (i >= 6) {
            // ---- dilation: vertical OR in regs, horizontal via parity smem ----
            unsigned v = e4_0 | e4_1 | e4_2 | e4_3 | e4_4;
            const int pb2 = i & 1;
            vbuf[pb2][1 + t] = v;
            __syncthreads();   // B: v row visible
            unsigned vL = vbuf[pb2][t], vR = vbuf[pb2][2 + t];
            unsigned d4 = v
                        | ((vL >> 16) | (v << 16))
                        | ((vL >> 24) | (v << 8))
                        | ((v >> 8)   | (vR << 24))
                        | ((v >> 16)  | (vR << 16));
            unsigned ed4 = e4_2 | (d4 << 1);   // e of row rd = rE-2 is e4_2

            const int iv = i - 6;
            const int rv = y0 - 3 + iv;        // = rd
            if (iv >= 3 && iv <= 34)
                *(unsigned*)(edout + rv * W_ + c0) = ed4;
            if (rv < 0 || rv >= H_) ed4 = 0x03030303u;  // OOB: both masks 0

            // ---- variance vertical update ----
            int sn = cur - 3;  if (sn < 0) sn += LRING;   // lum[rv]
            int so = cur - 10; if (so < 0) so += LRING;   // lum[rv-7]
            float4 xv  = *(const float4*)&slum[sn][4 + c0];
            float4 xo4 = *(const float4*)&slum[so][4 + c0];
#pragma unroll
            for (int c = 0; c < 4; c++) {
                unsigned bn = (ed4  >> (8 * c)) & 3u;
                unsigned bo = (edr0 >> (8 * c)) & 3u;
                float xn  = (&xv.x)[c];
                float xo  = (&xo4.x)[c];
                float mpn = (bn == 2u) ? 1.f : 0.f;
                float mbn = (bn == 0u) ? 1.f : 0.f;
                float mpo = (bo == 2u) ? 1.f : 0.f;
                float mbo = (bo == 0u) ? 1.f : 0.f;
                vs[0][c] += mpn - mpo;
                vs[1][c] += xn * mpn - xo * mpo;
                vs[2][c] += xn * xn * mpn - xo * xo * mpo;
                vs[3][c] += mbn - mbo;
                vs[4][c] += xn * mbn - xo * mbo;
                vs[5][c] += xn * xn * mbn - xo * xo * mbo;
            }
            edr0 = edr1; edr1 = edr2; edr2 = edr3;
            edr3 = edr4; edr4 = edr5; edr5 = edr6; edr6 = ed4;

            // ---- horizontal 7-tap + masked accumulate (output row rv-3) ----
            if (iv >= 6) {
                const int par = iv & 1;
                if (l == 31) {
#pragma unroll
                    for (int q = 0; q < 6; q++) {
                        sufB[par][w][q][0] = vs[q][1] + vs[q][2] + vs[q][3];
                        sufB[par][w][q][1] = vs[q][2] + vs[q][3];
                        sufB[par][w][q][2] = vs[q][3];
                    }
                }
                if (l == 0) {
#pragma unroll
                    for (int q = 0; q < 6; q++) {
                        preB[par][w][q][0] = vs[q][0];
                        preB[par][w][q][1] = vs[q][0] + vs[q][1];
                        preB[par][w][q][2] = vs[q][0] + vs[q][1] + vs[q][2];
                    }
                }
                __syncthreads();   // C: halos visible

                unsigned edc = edr3;           // center row rv-3
#pragma unroll
                for (int g = 0; g < 2; g++) {
                    float Wn[3][4];
#pragma unroll
                    for (int qq = 0; qq < 3; qq++) {
                        const int q = 3 * g + qq;
                        float p0 = vs[q][0];
                        float p1 = p0 + vs[q][1];
                        float p2 = p1 + vs[q][2];
                        float T  = p2 + vs[q][3];
                        float s1 = T - p0, s2 = T - p1, s3 = T - p2;
                        float ls1 = __shfl_up_sync(0xffffffffu, s1, 1);
                        float ls2 = __shfl_up_sync(0xffffffffu, s2, 1);
                        float ls3 = __shfl_up_sync(0xffffffffu, s3, 1);
                        float rp0 = __shfl_down_sync(0xffffffffu, p0, 1);
                        float rp1 = __shfl_down_sync(0xffffffffu, p1, 1);
                        float rp2 = __shfl_down_sync(0xffffffffu, p2, 1);
                        if (l == 0) {
                            ls1 = (w > 0) ? sufB[par][w - 1][q][0] : 0.f;
                            ls2 = (w > 0) ? sufB[par][w - 1][q][1] : 0.f;
                            ls3 = (w > 0) ? sufB[par][w - 1][q][2] : 0.f;
                        }
                        if (l == 31) {
                            rp0 = (w < 3) ? preB[par][w + 1][q][0] : 0.f;
                            rp1 = (w < 3) ? preB[par][w + 1][q][1] : 0.f;
                            rp2 = (w < 3) ? preB[par][w + 1][q][2] : 0.f;
                        }
                        Wn[qq][0] = ls1 + T;
                        Wn[qq][1] = ls2 + T + rp0;
                        Wn[qq][2] = ls3 + T + rp1;
                        Wn[qq][3] = T + rp2;
                    }
                    float aV = 0.f, aN = 0.f;
#pragma unroll
                    for (int c = 0; c < 4; c++) {
                        float cnt = fmaxf(Wn[0][c], 1.f);
                        float rcn = __fdividef(1.f, cnt);
                        float mu  = Wn[1][c] * rcn;
                        float var = fmaxf(Wn[2][c] * rcn - mu * mu, 0.f);
                        unsigned bc = (edc >> (8 * c)) & 3u;
                        float m = (g == 0) ? ((bc == 2u) ? 1.f : 0.f)
                                           : ((bc == 0u) ? 1.f : 0.f);
                        aV += m * var; aN += m;
                    }
                    if (g == 0) { accVp += aV; accNp += aN; }
                    else        { accVb += aV; accNb += aN; }
                }
            }
        }

        cur++; if (cur == LRING) cur = 0;
    }

    // ---- warp reduce + one atomic per warp per scalar ----
#pragma unroll
    for (int off = 16; off > 0; off >>= 1) {
        accVp += __shfl_down_sync(0xffffffffu, accVp, off);
        accNp += __shfl_down_sync(0xffffffffu, accNp, off);
        accVb += __shfl_down_sync(0xffffffffu, accVb, off);
        accNb += __shfl_down_sync(0xffffffffu, accNb, off);
    }
    if (l == 0) {
        atomicAdd(&g_acc[img * 4 + 0], accVp);
        atomicAdd(&g_acc[img * 4 + 1], accNp);
        atomicAdd(&g_acc[img * 4 + 2], accVb);
        atomicAdd(&g_acc[img * 4 + 3], accNb);
    }
}

// ---------------- K2: flags + output = clip(ringing_tgt - ringing_ref, 0) ---
__global__ void k_output(float* __restrict__ out)
{
    int idx = blockIdx.x * blockDim.x + threadIdx.x;
    const int n4 = B_ * HW_ / 4;
    if (idx >= n4) return;
    int b  = idx / (HW_ / 4);
    int p4 = idx % (HW_ / 4);

    float vpr = g_acc[b * 4 + 0],        npr = g_acc[b * 4 + 1];
    float vbr = g_acc[b * 4 + 2],        nbr = g_acc[b * 4 + 3];
    float vpt = g_acc[(b + B_) * 4 + 0], npt = g_acc[(b + B_) * 4 + 1];
    float vbt = g_acc[(b + B_) * 4 + 2], nbt = g_acc[(b + B_) * 4 + 3];
    float fr = ((vpr / fmaxf(npr, 1.f)) / (vbr / fmaxf(nbr, 1.f) + 1e-12f) > 2.0f) ? 1.f : 0.f;
    float ft = ((vpt / fmaxf(npt, 1.f)) / (vbt / fmaxf(nbt, 1.f) + 1e-12f) > 2.0f) ? 1.f : 0.f;

    const uchar4* edr4 = (const uchar4*)(g_ed + (size_t)b * HW_);
    const uchar4* edt4 = (const uchar4*)(g_ed + (size_t)(b + B_) * HW_);
    uchar4 r4 = edr4[p4], t4 = edt4[p4];

    // byte==2 (d=1,e=0) <=> pixel in M_prox
    float4 o;
    o.x = fmaxf((t4.x == 2 ? ft : 0.f) - (r4.x == 2 ? fr : 0.f), 0.f);
    o.y = fmaxf((t4.y == 2 ? ft : 0.f) - (r4.y == 2 ? fr : 0.f), 0.f);
    o.z = fmaxf((t4.z == 2 ? ft : 0.f) - (r4.z == 2 ? fr : 0.f), 0.f);
    o.w = fmaxf((t4.w == 2 ? ft : 0.f) - (r4.w == 2 ? fr : 0.f), 0.f);
    ((float4*)out)[idx] = o;
}

// ---------------- K3: epilogue — re-zero g_acc for the next (graph) call ----
// g_acc is zero at module load (first call) and re-zeroed here after use, so
// every invocation sees identical state: deterministic across graph replays.
__global__ void k_zero_acc()
{
    if (threadIdx.x < NIMG * 4) g_acc[threadIdx.x] = 0.f;
}

// ---------------- launch ----------------
extern "C" void kernel_launch(void* const* d_in, const int* in_sizes, int n_in,
                              void* d_out, int out_size)
{
    const float* ref = (const float*)d_in[0];
    const float* tgt = (const float*)d_in[1];

    k_fused<<<dim3(16, NIMG), 128>>>(ref, tgt);

    const int n4 = B_ * HW_ / 4;
    k_output<<<(n4 + 255) / 256, 256>>>((float*)d_out);

    k_zero_acc<<<1, 128>>>();
}